// round 14
// baseline (speedup 1.0000x reference)
#include <cuda_runtime.h>
#include <cuda_fp16.h>
#include <cstdint>

namespace {
constexpr int B_ = 8, N_ = 1024, DIM = 512, H_ = 8, DH = 64, INNER = 512, G = 64;
constexpr float SCALE = 0.125f;
constexpr float LOG2E = 1.4426950408889634f;
}

// Scratch (device globals — allocation-free rule)
__device__ float g_q[(size_t)G * N_ * DH];
__device__ float g_k[(size_t)G * N_ * DH];
__device__ float g_vT[(size_t)G * DH * N_];        // V transposed: [g][d][j]
__device__ float g_ml[G * N_];   // log2-domain lidar logit upper bound
__device__ float g_isl[G * N_];  // 1 / sum exp2(lidar - bound)
__device__ float g_mi[G * N_];   // per-row upper bound of blended logit (log2)
__device__ float g_w2[DIM * INNER];
__device__ float g_b2[DIM];
__device__ float g_oacc[2 * (size_t)G * N_ * DH];  // split-KV partial O
__device__ float g_lacc[2 * G * N_];               // partial row sums -> linv

// ---------------------------------------------------------------------------
// helpers
// ---------------------------------------------------------------------------
__device__ __forceinline__ float ex2f(float x) {
    float y;
    asm("ex2.approx.f32 %0, %1;" : "=f"(y) : "f"(x));
    return y;
}

__device__ __forceinline__ void mma16(float* d, const unsigned* a,
                                      const unsigned* b) {
    asm("mma.sync.aligned.m16n8k16.row.col.f32.f16.f16.f32 "
        "{%0,%1,%2,%3}, {%4,%5,%6,%7}, {%8,%9}, {%0,%1,%2,%3};"
        : "+f"(d[0]), "+f"(d[1]), "+f"(d[2]), "+f"(d[3])
        : "r"(a[0]), "r"(a[1]), "r"(a[2]), "r"(a[3]), "r"(b[0]), "r"(b[1]));
}

__device__ __forceinline__ void ldsm4(unsigned* r, uint32_t a) {
    asm volatile(
        "ldmatrix.sync.aligned.m8n8.x4.shared.b16 {%0,%1,%2,%3}, [%4];"
        : "=r"(r[0]), "=r"(r[1]), "=r"(r[2]), "=r"(r[3]) : "r"(a));
}
__device__ __forceinline__ void ldsm2(unsigned* r, uint32_t a) {
    asm volatile(
        "ldmatrix.sync.aligned.m8n8.x2.shared.b16 {%0,%1}, [%2];"
        : "=r"(r[0]), "=r"(r[1]) : "r"(a));
}

// fp16 tile mma via ldmatrix. A: [rows][ASTR] halves (k contiguous),
// B: [n][BSTR] halves (k contiguous). Fragment order matches mma16.
template <int MT, int NT, int WARPS_N, int KS, int ASTR, int BSTR>
__device__ __forceinline__ void mma_h(const __half* As, const __half* Bs,
                                      int warp, int lane,
                                      float (&acc)[MT][NT][4]) {
    const int wm = warp / WARPS_N, wn = warp % WARPS_N;
    const int arow = (lane & 7) + ((lane >> 3) & 1) * 8;
    const int acol = (lane >> 4) * 8;
    const int brow = lane & 7;
    const int bcol = ((lane >> 3) & 1) * 8;
    const uint32_t abase = (uint32_t)__cvta_generic_to_shared(
        As + (wm * (MT * 16) + arow) * ASTR + acol);
    const uint32_t bbase = (uint32_t)__cvta_generic_to_shared(
        Bs + (wn * (NT * 8) + brow) * BSTR + bcol);
#pragma unroll
    for (int ks = 0; ks < KS; ks++) {
        unsigned af[MT][4], bf[NT][2];
#pragma unroll
        for (int mt = 0; mt < MT; mt++)
            ldsm4(af[mt], abase + (mt * 16 * ASTR + ks * 16) * 2);
#pragma unroll
        for (int nt = 0; nt < NT; nt++)
            ldsm2(bf[nt], bbase + (nt * 8 * BSTR + ks * 16) * 2);
#pragma unroll
        for (int mt = 0; mt < MT; mt++)
#pragma unroll
            for (int nt = 0; nt < NT; nt++)
                mma16(acc[mt][nt], af[mt], bf[nt]);
    }
}

struct R4T { float4 a[4]; };
__device__ __forceinline__ void ldg4(R4T& r, const float* g, int ld) {
    const int t = threadIdx.x;
    const int rr = t >> 3, c4 = (t & 7) * 4;
#pragma unroll
    for (int p = 0; p < 4; p++)
        r.a[p] = *(const float4*)(g + (size_t)(rr + p * 32) * ld + c4);
}
template <int STRH, int COFF>
__device__ __forceinline__ void sts4h(__half* S, const R4T& r, float scale) {
    const int t = threadIdx.x;
    const int rr = t >> 3, c4 = (t & 7) * 4;
#pragma unroll
    for (int p = 0; p < 4; p++) {
        int row = rr + p * 32;
        float4 v = r.a[p];
        __half* rp = S + row * STRH + COFF + c4;
        *(__half2*)rp = __floats2half2_rn(v.x * scale, v.y * scale);
        *(__half2*)(rp + 2) = __floats2half2_rn(v.z * scale, v.w * scale);
    }
}

// ---------------------------------------------------------------------------
// K1: qkv = x @ w_qkv^T -> head-major q/k + transposed vT  (fp16 HMMA)
// ---------------------------------------------------------------------------
__global__ __launch_bounds__(256) void k_qkv(const float* __restrict__ x,
                                             const float* __restrict__ w) {
    __shared__ __half As[2][128 * 40], Bs[2][128 * 40];
    const int t = threadIdx.x, warp = t >> 5, lane = t & 31;
    const int g8 = lane >> 2, t4 = lane & 3;
    const int n0 = blockIdx.x * 128, m0 = blockIdx.y * 128;
    float acc[4][4][4] = {};
    R4T ra, rb;
    ldg4(ra, x + (size_t)m0 * DIM, DIM);
    ldg4(rb, w + (size_t)n0 * DIM, DIM);
    sts4h<40, 0>(As[0], ra, 1.f);
    sts4h<40, 0>(Bs[0], rb, 1.f);
    __syncthreads();
    int cur = 0;
    for (int k0 = 32; k0 < DIM; k0 += 32) {
        ldg4(ra, x + (size_t)m0 * DIM + k0, DIM);
        ldg4(rb, w + (size_t)n0 * DIM + k0, DIM);
        mma_h<4, 4, 4, 2, 40, 40>(As[cur], Bs[cur], warp, lane, acc);
        sts4h<40, 0>(As[cur ^ 1], ra, 1.f);
        sts4h<40, 0>(Bs[cur ^ 1], rb, 1.f);
        __syncthreads();
        cur ^= 1;
    }
    mma_h<4, 4, 4, 2, 40, 40>(As[cur], Bs[cur], warp, lane, acc);
    const int wm = warp >> 2, wn = warp & 3;
#pragma unroll
    for (int mt = 0; mt < 4; mt++)
#pragma unroll
        for (int nt = 0; nt < 4; nt++) {
            int col = n0 + wn * 32 + nt * 8 + 2 * t4;
            int part = col >> 9, h = (col >> 6) & 7, d = col & 63;
#pragma unroll
            for (int half = 0; half < 2; half++) {
                int row = m0 + wm * 64 + mt * 16 + g8 + half * 8;
                int b = row >> 10, n = row & 1023;
                float2 val = half ? make_float2(acc[mt][nt][2], acc[mt][nt][3])
                                  : make_float2(acc[mt][nt][0], acc[mt][nt][1]);
                if (part == 2) {
                    float* dT = g_vT + ((size_t)((b * 8 + h) * 64 + d)) * 1024 + n;
                    dT[0] = val.x;
                    dT[1024] = val.y;
                } else {
                    float* dst = part == 0 ? g_q : g_k;
                    *(float2*)&dst[((size_t)((b * 8 + h) * 1024 + n)) * 64 + d] = val;
                }
            }
        }
}

// ---------------------------------------------------------------------------
// K1b (merged bounds): y==0 -> blended-logit bound (g_mi); y==1 -> lidar (g_ml)
// ---------------------------------------------------------------------------
__global__ __launch_bounds__(256) void k_bounds(const float* __restrict__ conv_w,
                                                const float* __restrict__ lidar) {
    __shared__ float nrm[1024];
    __shared__ float red[8];
    __shared__ float smax;
    const int g = blockIdx.x, t = threadIdx.x;
    const int b = g >> 3, h = g & 7;
    if (blockIdx.y == 0) {
        const float* kb = g_k + (size_t)g * N_ * DH;
        float mx = 0.f;
        for (int j = t; j < N_; j += 256) {
            const float4* r4 = (const float4*)(kb + (size_t)j * DH);
            float s = 0.f;
#pragma unroll
            for (int q = 0; q < 16; q++) {
                float4 v = r4[q];
                s += v.x * v.x + v.y * v.y + v.z * v.z + v.w * v.w;
            }
            mx = fmaxf(mx, s);
        }
        for (int o = 16; o; o >>= 1) mx = fmaxf(mx, __shfl_xor_sync(~0u, mx, o));
        if ((t & 31) == 0) red[t >> 5] = mx;
        __syncthreads();
        if (t == 0) {
            float m = red[0];
#pragma unroll
            for (int w = 1; w < 8; w++) m = fmaxf(m, red[w]);
            smax = m;
        }
        __syncthreads();
        const float maxkk = smax;
        const float c0a = fabsf(conv_w[0]) * SCALE * LOG2E;
        const float c1L = conv_w[1] * LOG2E;
        const float* qb = g_q + (size_t)g * N_ * DH;
        for (int i = t; i < N_; i += 256) {
            const float4* r4 = (const float4*)(qb + (size_t)i * DH);
            float s = 0.f;
#pragma unroll
            for (int q = 0; q < 16; q++) {
                float4 v = r4[q];
                s += v.x * v.x + v.y * v.y + v.z * v.z + v.w * v.w;
            }
            g_mi[g * N_ + i] = c0a * sqrtf(s * maxkk) + fmaxf(c1L, 0.f);
        }
    } else {
        const float* base = lidar + (size_t)b * N_ * INNER + h * 64;
        for (int i = t; i < N_; i += 256) {
            const float4* r4 = (const float4*)(base + (size_t)i * INNER);
            float s = 0.f;
#pragma unroll
            for (int q = 0; q < 16; q++) {
                float4 v = r4[q];
                s += v.x * v.x + v.y * v.y + v.z * v.z + v.w * v.w;
            }
            nrm[i] = sqrtf(s);
        }
        __syncthreads();
        float mx = 0.f;
        for (int i = t; i < N_; i += 256) mx = fmaxf(mx, nrm[i]);
        for (int o = 16; o; o >>= 1) mx = fmaxf(mx, __shfl_xor_sync(~0u, mx, o));
        if ((t & 31) == 0) red[t >> 5] = mx;
        __syncthreads();
        if (t == 0) {
            float m = red[0];
#pragma unroll
            for (int w = 1; w < 8; w++) m = fmaxf(m, red[w]);
            smax = m;
        }
        __syncthreads();
        const float c = SCALE * LOG2E * smax;
        for (int i = t; i < N_; i += 256)
            g_ml[g * N_ + i] = c * nrm[i];
    }
}

// ---------------------------------------------------------------------------
// K2 (lstats): lidar row sums with fixed bound. fp16+LDSM, 1 sync/iter.
// ---------------------------------------------------------------------------
__global__ __launch_bounds__(256) void k_lstats(const float* __restrict__ lidar) {
    extern __shared__ __half smh[];
    __half* Ali = smh;                    // 128*72
    __half* BsA = smh + 9216;             // 2 x 128*72
    float* mls = (float*)(smh + 27648);
    float* red = mls + 128;               // 512
    const int t = threadIdx.x, warp = t >> 5, lane = t & 31;
    const int g8 = lane >> 2, t4 = lane & 3;
    const int gidx = blockIdx.y, b = gidx >> 3, h = gidx & 7;
    const int i0 = blockIdx.x * 128;
    const float* base = lidar + (size_t)b * N_ * INNER + h * 64;
    const int wm = warp >> 2, wn = warp & 3;
    R4T ra, rb;
    ldg4(ra, base + (size_t)i0 * INNER, INNER);
    sts4h<72, 0>(Ali, ra, SCALE * LOG2E);
    ldg4(ra, base + (size_t)i0 * INNER + 32, INNER);
    sts4h<72, 32>(Ali, ra, SCALE * LOG2E);
    if (t < 128) mls[t] = g_ml[gidx * N_ + i0 + t];
    ldg4(ra, base, INNER);
    ldg4(rb, base + 32, INNER);
    sts4h<72, 0>(BsA, ra, 1.f);
    sts4h<72, 32>(BsA, rb, 1.f);
    ldg4(ra, base + (size_t)128 * INNER, INNER);
    ldg4(rb, base + (size_t)128 * INNER + 32, INNER);
    __syncthreads();
    int cur = 0;
    float lp[4][2] = {};
    for (int jt = 0; jt < 8; jt++) {
        __half* bnext = BsA + (cur ^ 1) * 9216;
        sts4h<72, 0>(bnext, ra, 1.f);
        sts4h<72, 32>(bnext, rb, 1.f);
        {
            const float* nxt = base + (size_t)(((jt + 2) & 7) * 128) * INNER;
            ldg4(ra, nxt, INNER);
            ldg4(rb, nxt + 32, INNER);
        }
        float acc[4][4][4] = {};
        mma_h<4, 4, 4, 4, 72, 72>(Ali, BsA + cur * 9216, warp, lane, acc);
#pragma unroll
        for (int mt = 0; mt < 4; mt++) {
            int r = wm * 64 + mt * 16 + g8;
            float mn0 = mls[r], mn1 = mls[r + 8];
            float s0 = 0.f, s1 = 0.f;
#pragma unroll
            for (int nt = 0; nt < 4; nt++) {
                s0 += ex2f(acc[mt][nt][0] - mn0) + ex2f(acc[mt][nt][1] - mn0);
                s1 += ex2f(acc[mt][nt][2] - mn1) + ex2f(acc[mt][nt][3] - mn1);
            }
            lp[mt][0] += s0; lp[mt][1] += s1;
        }
        __syncthreads();
        cur ^= 1;
    }
#pragma unroll
    for (int mt = 0; mt < 4; mt++) {
        float s0 = lp[mt][0], s1 = lp[mt][1];
#pragma unroll
        for (int off = 1; off <= 2; off <<= 1) {
            s0 += __shfl_xor_sync(~0u, s0, off);
            s1 += __shfl_xor_sync(~0u, s1, off);
        }
        if (t4 == 0) {
            red[wn * 128 + wm * 64 + mt * 16 + g8] = s0;
            red[wn * 128 + wm * 64 + mt * 16 + g8 + 8] = s1;
        }
    }
    __syncthreads();
    if (t < 128)
        g_isl[gidx * N_ + i0 + t] =
            1.0f / (red[t] + red[128 + t] + red[256 + t] + red[384 + t]);
}

// ---------------------------------------------------------------------------
// K3 (flash, split-KV, fp16+LDSM): 3 barriers/iter, no in-loop reductions.
// ---------------------------------------------------------------------------
__global__ __launch_bounds__(256, 1) void k_flash(const float* __restrict__ lidar,
                                                  const float* __restrict__ conv_w) {
    extern __shared__ __half smh[];
    __half* AliL = smh;                   // 128*72
    __half* AliQ = smh + 9216;            // 128*72
    __half* Bs0  = smh + 18432;           // 128*72
    __half* Bs1  = smh + 27648;           // 128*72
    __half* Vs   = smh + 36864;           // 64*136 (d-major, j contiguous)
    __half* Ps   = smh + 45568;           // 128*136
    float* mls  = (float*)(smh + 62976);
    float* isls = mls + 128;
    float* m_s  = isls + 128;
    float* red  = m_s + 128;              // 512

    const int t = threadIdx.x, warp = t >> 5, lane = t & 31;
    const int g8 = lane >> 2, t4 = lane & 3;
    const int gidx = blockIdx.y, i0 = blockIdx.x * 128;
    const int jh = blockIdx.z;
    const int b = gidx >> 3, h = gidx & 7;
    const float c0s = conv_w[0] * SCALE * LOG2E;
    const float c1L = conv_w[1] * LOG2E;
    const int wm = warp >> 2, wn = warp & 3;
    const int wm2 = warp >> 1, wn2 = warp & 1;

    if (t < 128) {
        mls[t] = g_ml[gidx * N_ + i0 + t];
        isls[t] = g_isl[gidx * N_ + i0 + t];
        m_s[t] = g_mi[gidx * N_ + i0 + t];
    }
    const float* lbase = lidar + (size_t)b * N_ * INNER + h * 64;
    const float* qb = g_q + (size_t)gidx * N_ * DH;
    const float* kb = g_k + (size_t)gidx * N_ * DH;
    const float* vb = g_vT + (size_t)gidx * DH * N_;

    R4T ra, rb;
    ldg4(ra, lbase + (size_t)i0 * INNER, INNER);      sts4h<72, 0>(AliL, ra, SCALE * LOG2E);
    ldg4(ra, lbase + (size_t)i0 * INNER + 32, INNER); sts4h<72, 32>(AliL, ra, SCALE * LOG2E);
    ldg4(ra, qb + (size_t)i0 * DH, DH);               sts4h<72, 0>(AliQ, ra, c0s);
    ldg4(ra, qb + (size_t)i0 * DH + 32, DH);          sts4h<72, 32>(AliQ, ra, c0s);
    const int jstart = jh * 512;
    ldg4(ra, lbase + (size_t)jstart * INNER, INNER);
    ldg4(rb, lbase + (size_t)jstart * INNER + 32, INNER);
    sts4h<72, 0>(Bs0, ra, 1.f);
    sts4h<72, 32>(Bs0, rb, 1.f);
    ldg4(ra, kb + (size_t)jstart * DH, DH);
    ldg4(rb, kb + (size_t)jstart * DH + 32, DH);
    __syncthreads();

    float acc_o[2][4][4] = {};
    float lp[4][2] = {};
    float4 vreg[8];

    const int vd = t >> 2;                 // 0..63
    const int vj = (t & 3) * 4;            // j base within 16-group

    for (int j0 = jstart; j0 < jstart + 512; j0 += 128) {
        float acc[4][4][4] = {};
        // --- step 1: lidar mma (Bs0); stage k (Bs1); ldg V
        mma_h<4, 4, 4, 4, 72, 72>(AliL, Bs0, warp, lane, acc);
#pragma unroll
        for (int mt = 0; mt < 4; mt++) {
            int r = wm * 64 + mt * 16 + g8;
            float m0v = mls[r], i0v = isls[r] * c1L;
            float m1v = mls[r + 8], i1v = isls[r + 8] * c1L;
#pragma unroll
            for (int nt = 0; nt < 4; nt++) {
                acc[mt][nt][0] = i0v * ex2f(acc[mt][nt][0] - m0v);
                acc[mt][nt][1] = i0v * ex2f(acc[mt][nt][1] - m0v);
                acc[mt][nt][2] = i1v * ex2f(acc[mt][nt][2] - m1v);
                acc[mt][nt][3] = i1v * ex2f(acc[mt][nt][3] - m1v);
            }
        }
        sts4h<72, 0>(Bs1, ra, 1.f);
        sts4h<72, 32>(Bs1, rb, 1.f);
        {
            const float* src = vb + (size_t)vd * N_ + j0 + vj;
#pragma unroll
            for (int q = 0; q < 8; q++)
                vreg[q] = *(const float4*)(src + q * 16);
        }
        __syncthreads();                               // (1)
        // --- step 2: qk mma (Bs1); P write; stage V; ldg next lidar
        mma_h<4, 4, 4, 4, 72, 72>(AliQ, Bs1, warp, lane, acc);
#pragma unroll
        for (int mt = 0; mt < 4; mt++) {
            int r = wm * 64 + mt * 16 + g8;
            float mn0 = m_s[r], mn1 = m_s[r + 8];
            float s0 = 0.f, s1 = 0.f;
#pragma unroll
            for (int nt = 0; nt < 4; nt++) {
                float p0 = ex2f(acc[mt][nt][0] - mn0);
                float p1 = ex2f(acc[mt][nt][1] - mn0);
                float p2 = ex2f(acc[mt][nt][2] - mn1);
                float p3 = ex2f(acc[mt][nt][3] - mn1);
                s0 += p0 + p1; s1 += p2 + p3;
                int gp = wn * 32 + nt * 8 + 2 * t4;
                *(__half2*)&Ps[r * 136 + gp] = __floats2half2_rn(p0, p1);
                *(__half2*)&Ps[(r + 8) * 136 + gp] = __floats2half2_rn(p2, p3);
            }
            lp[mt][0] += s0; lp[mt][1] += s1;
        }
#pragma unroll
        for (int q = 0; q < 8; q++) {
            float4 v = vreg[q];
            __half* rp = Vs + vd * 136 + vj + q * 16;
            *(__half2*)rp = __floats2half2_rn(v.x, v.y);
            *(__half2*)(rp + 2) = __floats2half2_rn(v.z, v.w);
        }
        {
            const float* nxt = lbase + (size_t)((j0 + 128) & (N_ - 1)) * INNER;
            ldg4(ra, nxt, INNER);
            ldg4(rb, nxt + 32, INNER);
        }
        __syncthreads();                               // (2)
        // --- step 3: PV mma; stage next lidar (Bs0); ldg next k
        mma_h<2, 4, 2, 8, 136, 136>(Ps, Vs, warp, lane, acc_o);
        sts4h<72, 0>(Bs0, ra, 1.f);
        sts4h<72, 32>(Bs0, rb, 1.f);
        {
            const float* nxt = kb + (size_t)((j0 + 128) & (N_ - 1)) * DH;
            ldg4(ra, nxt, DH);
            ldg4(rb, nxt + 32, DH);
        }
        __syncthreads();                               // (3)
    }
    // final partial row-sum reduction
#pragma unroll
    for (int mt = 0; mt < 4; mt++) {
        float s0 = lp[mt][0], s1 = lp[mt][1];
#pragma unroll
        for (int off = 1; off <= 2; off <<= 1) {
            s0 += __shfl_xor_sync(~0u, s0, off);
            s1 += __shfl_xor_sync(~0u, s1, off);
        }
        if (t4 == 0) {
            red[wn * 128 + wm * 64 + mt * 16 + g8] = s0;
            red[wn * 128 + wm * 64 + mt * 16 + g8 + 8] = s1;
        }
    }
    __syncthreads();
    if (t < 128)
        g_lacc[jh * G * N_ + gidx * N_ + i0 + t] =
            red[t] + red[128 + t] + red[256 + t] + red[384 + t];
    float* ob = g_oacc + (size_t)jh * G * N_ * DH + ((size_t)gidx * N_ + i0) * DH;
#pragma unroll
    for (int mt = 0; mt < 2; mt++) {
        int r = wm2 * 32 + mt * 16 + g8;
#pragma unroll
        for (int nt = 0; nt < 4; nt++) {
            int d = wn2 * 32 + nt * 8 + 2 * t4;
            *(float2*)&ob[(size_t)r * DH + d] =
                make_float2(acc_o[mt][nt][0], acc_o[mt][nt][1]);
            *(float2*)&ob[(size_t)(r + 8) * DH + d] =
                make_float2(acc_o[mt][nt][2], acc_o[mt][nt][3]);
        }
    }
}

// ---------------------------------------------------------------------------
// K3b: linv = 1/(l0+l1)  (overwrites g_lacc[0..G*N))
// ---------------------------------------------------------------------------
__global__ __launch_bounds__(256) void k_linv() {
    int i = blockIdx.x * 256 + threadIdx.x;
    g_lacc[i] = 1.0f / (g_lacc[i] + g_lacc[G * N_ + i]);
}

// ---------------------------------------------------------------------------
// K4: out = combined(Oacc) @ W2^T + bias2  (fp16 HMMA + fused combine)
// ---------------------------------------------------------------------------
__device__ __forceinline__ void ldg4_y(R4T& r, int m0, int k0) {
    const int t = threadIdx.x;
    const int rr = t >> 3, c4 = (t & 7) * 4;
    const int kk = k0 + c4;
#pragma unroll
    for (int p = 0; p < 4; p++) {
        int m = m0 + rr + p * 32;
        int bb = m >> 10, n = m & 1023;
        int g = bb * 8 + (kk >> 6), d = kk & 63;
        size_t off = ((size_t)g * N_ + n) * DH + d;
        float4 o0 = *(const float4*)&g_oacc[off];
        float4 o1 = *(const float4*)&g_oacc[(size_t)G * N_ * DH + off];
        float inv = g_lacc[g * N_ + n];
        r.a[p] = make_float4((o0.x + o1.x) * inv, (o0.y + o1.y) * inv,
                             (o0.z + o1.z) * inv, (o0.w + o1.w) * inv);
    }
}

__global__ __launch_bounds__(256) void k_out(float* __restrict__ out) {
    __shared__ __half As[2][128 * 40], Bs[2][128 * 40];
    const int t = threadIdx.x, warp = t >> 5, lane = t & 31;
    const int g8 = lane >> 2, t4 = lane & 3;
    const int n0 = blockIdx.x * 128, m0 = blockIdx.y * 128;
    float acc[4][4][4] = {};
    R4T ra, rb;
    ldg4_y(ra, m0, 0);
    ldg4(rb, g_w2 + (size_t)n0 * INNER, INNER);
    sts4h<40, 0>(As[0], ra, 1.f);
    sts4h<40, 0>(Bs[0], rb, 1.f);
    __syncthreads();
    int cur = 0;
    for (int k0 = 32; k0 < INNER; k0 += 32) {
        ldg4_y(ra, m0, k0);
        ldg4(rb, g_w2 + (size_t)n0 * INNER + k0, INNER);
        mma_h<4, 4, 4, 2, 40, 40>(As[cur], Bs[cur], warp, lane, acc);
        sts4h<40, 0>(As[cur ^ 1], ra, 1.f);
        sts4h<40, 0>(Bs[cur ^ 1], rb, 1.f);
        __syncthreads();
        cur ^= 1;
    }
    mma_h<4, 4, 4, 2, 40, 40>(As[cur], Bs[cur], warp, lane, acc);
    const int wm = warp >> 2, wn = warp & 3;
#pragma unroll
    for (int mt = 0; mt < 4; mt++)
#pragma unroll
        for (int nt = 0; nt < 4; nt++) {
            int col = n0 + wn * 32 + nt * 8 + 2 * t4;
            float b0 = g_b2[col], b1 = g_b2[col + 1];
            int r = m0 + wm * 64 + mt * 16 + g8;
            *(float2*)&out[(size_t)r * DIM + col] =
                make_float2(acc[mt][nt][0] + b0, acc[mt][nt][1] + b1);
            *(float2*)&out[(size_t)(r + 8) * DIM + col] =
                make_float2(acc[mt][nt][2] + b0, acc[mt][nt][3] + b1);
        }
}

// ---------------------------------------------------------------------------
// Precompute: W2 = Wout(.,h-block) @ Wm ; bias2 = b_out + Wout b_merge~
// ---------------------------------------------------------------------------
__global__ __launch_bounds__(256) void k_w2(const float* __restrict__ w_merge,
                                            const float* __restrict__ w_out) {
    __shared__ float wm[64 * 64];
    const int t = threadIdx.x;
    for (int i = t; i < 4096; i += 256) wm[i] = w_merge[i];
    __syncthreads();
    int idx = blockIdx.x * 256 + t;
    int c = idx >> 9, i = idx & 511;
    int h = i >> 6, d = i & 63;
    const float* wo = w_out + (size_t)c * INNER + h * 64;
    float s = 0.f;
#pragma unroll 8
    for (int dp = 0; dp < 64; dp++) s += wo[dp] * wm[dp * 64 + d];
    g_w2[idx] = s;
}

__global__ __launch_bounds__(256) void k_bias2(const float* __restrict__ w_out,
                                               const float* __restrict__ b_merge,
                                               const float* __restrict__ b_out) {
    int c = blockIdx.x * 8 + (threadIdx.x >> 5);
    int lane = threadIdx.x & 31;
    float s = 0.f;
    for (int i = lane; i < INNER; i += 32)
        s += w_out[(size_t)c * INNER + i] * b_merge[i & 63];
    for (int o = 16; o; o >>= 1) s += __shfl_xor_sync(~0u, s, o);
    if (lane == 0) g_b2[c] = b_out[c] + s;
}

__global__ __launch_bounds__(256) void k_copy(const float* __restrict__ src,
                                              float* __restrict__ dst, int n4) {
    int i = blockIdx.x * blockDim.x + threadIdx.x;
    if (i < n4) ((float4*)dst)[i] = ((const float4*)src)[i];
}

extern "C" void kernel_launch(void* const* d_in, const int* in_sizes, int n_in,
                              void* d_out, int out_size) {
    const float* x       = (const float*)d_in[0];
    const float* lidar   = (const float*)d_in[1];
    const float* w_qkv   = (const float*)d_in[2];
    const float* w_merge = (const float*)d_in[3];
    const float* b_merge = (const float*)d_in[4];
    const float* w_out   = (const float*)d_in[5];
    const float* b_out   = (const float*)d_in[6];
    const float* conv_w  = (const float*)d_in[7];
    float* out = (float*)d_out;

    const int flashSmem = 62976 * 2 + (3 * 128 + 512) * 4;   // ~129.5 KB
    const int lstatsSmem = 27648 * 2 + (128 + 512) * 4;      // ~57.9 KB
    cudaFuncSetAttribute(k_flash, cudaFuncAttributeMaxDynamicSharedMemorySize,
                         flashSmem);
    cudaFuncSetAttribute(k_lstats, cudaFuncAttributeMaxDynamicSharedMemorySize,
                         lstatsSmem);

    // launch order keeps k_flash 4th (ncu captures launch #4)
    k_qkv<<<dim3(12, 64), 256>>>(x, w_qkv);
    k_bounds<<<dim3(G, 2), 256>>>(conv_w, lidar);
    k_lstats<<<dim3(8, G), 256, lstatsSmem>>>(lidar);
    k_flash<<<dim3(8, G, 2), 256, flashSmem>>>(lidar, conv_w);
    k_linv<<<G * N_ / 256, 256>>>();
    k_w2<<<1024, 256>>>(w_merge, w_out);
    k_bias2<<<64, 256>>>(w_out, b_merge, b_out);
    k_out<<<dim3(4, 64), 256>>>(out);

    const int outElems = B_ * N_ * DIM;
    if (out_size >= 2 * outElems)
        k_copy<<<(outElems / 4 + 255) / 256, 256>>>(lidar, out + outElems,
                                                    outElems / 4);
}

// round 17
// speedup vs baseline: 1.0041x; 1.0041x over previous
#include <cuda_runtime.h>
#include <cuda_fp16.h>
#include <cstdint>

namespace {
constexpr int B_ = 8, N_ = 1024, DIM = 512, H_ = 8, DH = 64, INNER = 512, G = 64;
constexpr float SCALE = 0.125f;
constexpr float LOG2E = 1.4426950408889634f;
}

// Scratch (device globals — allocation-free rule)
__device__ float g_q[(size_t)G * N_ * DH];
__device__ float g_k[(size_t)G * N_ * DH];
__device__ float g_vT[(size_t)G * DH * N_];        // V transposed: [g][d][j]
__device__ float g_y[(size_t)B_ * N_ * INNER];
__device__ float g_ml[G * N_];   // log2-domain lidar logit upper bound
__device__ float g_isl[G * N_];  // 1 / sum exp2(lidar - bound)
__device__ float g_mi[G * N_];   // per-row upper bound of blended logit (log2)
__device__ float g_w2[DIM * INNER];
__device__ float g_b2[DIM];
__device__ float g_oacc[2 * (size_t)G * N_ * DH];  // split-KV partial O
__device__ float g_lacc[2 * G * N_];               // split-KV partial row sums

// ---------------------------------------------------------------------------
// helpers
// ---------------------------------------------------------------------------
__device__ __forceinline__ float ex2f(float x) {
    float y;
    asm("ex2.approx.f32 %0, %1;" : "=f"(y) : "f"(x));
    return y;
}

__device__ __forceinline__ void mma16(float* d, const unsigned* a,
                                      const unsigned* b) {
    asm("mma.sync.aligned.m16n8k16.row.col.f32.f16.f16.f32 "
        "{%0,%1,%2,%3}, {%4,%5,%6,%7}, {%8,%9}, {%0,%1,%2,%3};"
        : "+f"(d[0]), "+f"(d[1]), "+f"(d[2]), "+f"(d[3])
        : "r"(a[0]), "r"(a[1]), "r"(a[2]), "r"(a[3]), "r"(b[0]), "r"(b[1]));
}

__device__ __forceinline__ void ldsm4(unsigned* r, uint32_t a) {
    asm volatile(
        "ldmatrix.sync.aligned.m8n8.x4.shared.b16 {%0,%1,%2,%3}, [%4];"
        : "=r"(r[0]), "=r"(r[1]), "=r"(r[2]), "=r"(r[3]) : "r"(a));
}
__device__ __forceinline__ void ldsm2(unsigned* r, uint32_t a) {
    asm volatile(
        "ldmatrix.sync.aligned.m8n8.x2.shared.b16 {%0,%1}, [%2];"
        : "=r"(r[0]), "=r"(r[1]) : "r"(a));
}

// fp16 tile mma via ldmatrix. A: [rows][ASTR] halves (k contiguous),
// B: [n][BSTR] halves (k contiguous).
template <int MT, int NT, int WARPS_N, int KS, int ASTR, int BSTR>
__device__ __forceinline__ void mma_h(const __half* As, const __half* Bs,
                                      int warp, int lane,
                                      float (&acc)[MT][NT][4]) {
    const int wm = warp / WARPS_N, wn = warp % WARPS_N;
    const int arow = (lane & 7) + ((lane >> 3) & 1) * 8;
    const int acol = (lane >> 4) * 8;
    const int brow = lane & 7;
    const int bcol = ((lane >> 3) & 1) * 8;
    const uint32_t abase = (uint32_t)__cvta_generic_to_shared(
        As + (wm * (MT * 16) + arow) * ASTR + acol);
    const uint32_t bbase = (uint32_t)__cvta_generic_to_shared(
        Bs + (wn * (NT * 8) + brow) * BSTR + bcol);
#pragma unroll
    for (int ks = 0; ks < KS; ks++) {
        unsigned af[MT][4], bf[NT][2];
#pragma unroll
        for (int mt = 0; mt < MT; mt++)
            ldsm4(af[mt], abase + (mt * 16 * ASTR + ks * 16) * 2);
#pragma unroll
        for (int nt = 0; nt < NT; nt++)
            ldsm2(bf[nt], bbase + (nt * 8 * BSTR + ks * 16) * 2);
#pragma unroll
        for (int mt = 0; mt < MT; mt++)
#pragma unroll
            for (int nt = 0; nt < NT; nt++)
                mma16(acc[mt][nt], af[mt], bf[nt]);
    }
}

struct R4T { float4 a[4]; };
__device__ __forceinline__ void ldg4(R4T& r, const float* g, int ld) {
    const int t = threadIdx.x;
    const int rr = t >> 3, c4 = (t & 7) * 4;
#pragma unroll
    for (int p = 0; p < 4; p++)
        r.a[p] = *(const float4*)(g + (size_t)(rr + p * 32) * ld + c4);
}
template <int STRH, int COFF>
__device__ __forceinline__ void sts4h(__half* S, const R4T& r, float scale) {
    const int t = threadIdx.x;
    const int rr = t >> 3, c4 = (t & 7) * 4;
#pragma unroll
    for (int p = 0; p < 4; p++) {
        int row = rr + p * 32;
        float4 v = r.a[p];
        __half* rp = S + row * STRH + COFF + c4;
        *(__half2*)rp = __floats2half2_rn(v.x * scale, v.y * scale);
        *(__half2*)(rp + 2) = __floats2half2_rn(v.z * scale, v.w * scale);
    }
}

// ---------------------------------------------------------------------------
// K1: qkv = x @ w_qkv^T -> head-major q/k + transposed vT  (fp16 HMMA)
// ---------------------------------------------------------------------------
__global__ __launch_bounds__(256) void k_qkv(const float* __restrict__ x,
                                             const float* __restrict__ w) {
    __shared__ __half As[2][128 * 40], Bs[2][128 * 40];
    const int t = threadIdx.x, warp = t >> 5, lane = t & 31;
    const int g8 = lane >> 2, t4 = lane & 3;
    const int n0 = blockIdx.x * 128, m0 = blockIdx.y * 128;
    float acc[4][4][4] = {};
    R4T ra, rb;
    ldg4(ra, x + (size_t)m0 * DIM, DIM);
    ldg4(rb, w + (size_t)n0 * DIM, DIM);
    sts4h<40, 0>(As[0], ra, 1.f);
    sts4h<40, 0>(Bs[0], rb, 1.f);
    __syncthreads();
    int cur = 0;
    for (int k0 = 32; k0 < DIM; k0 += 32) {
        ldg4(ra, x + (size_t)m0 * DIM + k0, DIM);
        ldg4(rb, w + (size_t)n0 * DIM + k0, DIM);
        mma_h<4, 4, 4, 2, 40, 40>(As[cur], Bs[cur], warp, lane, acc);
        sts4h<40, 0>(As[cur ^ 1], ra, 1.f);
        sts4h<40, 0>(Bs[cur ^ 1], rb, 1.f);
        __syncthreads();
        cur ^= 1;
    }
    mma_h<4, 4, 4, 2, 40, 40>(As[cur], Bs[cur], warp, lane, acc);
    const int wm = warp >> 2, wn = warp & 3;
#pragma unroll
    for (int mt = 0; mt < 4; mt++)
#pragma unroll
        for (int nt = 0; nt < 4; nt++) {
            int col = n0 + wn * 32 + nt * 8 + 2 * t4;
            int part = col >> 9, h = (col >> 6) & 7, d = col & 63;
#pragma unroll
            for (int half = 0; half < 2; half++) {
                int row = m0 + wm * 64 + mt * 16 + g8 + half * 8;
                int b = row >> 10, n = row & 1023;
                float2 val = half ? make_float2(acc[mt][nt][2], acc[mt][nt][3])
                                  : make_float2(acc[mt][nt][0], acc[mt][nt][1]);
                if (part == 2) {
                    float* dT = g_vT + ((size_t)((b * 8 + h) * 64 + d)) * 1024 + n;
                    dT[0] = val.x;
                    dT[1024] = val.y;
                } else {
                    float* dst = part == 0 ? g_q : g_k;
                    *(float2*)&dst[((size_t)((b * 8 + h) * 1024 + n)) * 64 + d] = val;
                }
            }
        }
}

// ---------------------------------------------------------------------------
// K1b (merged bounds): y==0 -> blended-logit bound (g_mi); y==1 -> lidar (g_ml)
// ---------------------------------------------------------------------------
__global__ __launch_bounds__(256) void k_bounds(const float* __restrict__ conv_w,
                                                const float* __restrict__ lidar) {
    __shared__ float nrm[1024];
    __shared__ float red[8];
    __shared__ float smax;
    const int g = blockIdx.x, t = threadIdx.x;
    const int b = g >> 3, h = g & 7;
    if (blockIdx.y == 0) {
        const float* kb = g_k + (size_t)g * N_ * DH;
        float mx = 0.f;
        for (int j = t; j < N_; j += 256) {
            const float4* r4 = (const float4*)(kb + (size_t)j * DH);
            float s = 0.f;
#pragma unroll
            for (int q = 0; q < 16; q++) {
                float4 v = r4[q];
                s += v.x * v.x + v.y * v.y + v.z * v.z + v.w * v.w;
            }
            mx = fmaxf(mx, s);
        }
        for (int o = 16; o; o >>= 1) mx = fmaxf(mx, __shfl_xor_sync(~0u, mx, o));
        if ((t & 31) == 0) red[t >> 5] = mx;
        __syncthreads();
        if (t == 0) {
            float m = red[0];
#pragma unroll
            for (int w = 1; w < 8; w++) m = fmaxf(m, red[w]);
            smax = m;
        }
        __syncthreads();
        const float maxkk = smax;
        const float c0a = fabsf(conv_w[0]) * SCALE * LOG2E;
        const float c1L = conv_w[1] * LOG2E;
        const float* qb = g_q + (size_t)g * N_ * DH;
        for (int i = t; i < N_; i += 256) {
            const float4* r4 = (const float4*)(qb + (size_t)i * DH);
            float s = 0.f;
#pragma unroll
            for (int q = 0; q < 16; q++) {
                float4 v = r4[q];
                s += v.x * v.x + v.y * v.y + v.z * v.z + v.w * v.w;
            }
            g_mi[g * N_ + i] = c0a * sqrtf(s * maxkk) + fmaxf(c1L, 0.f);
        }
    } else {
        const float* base = lidar + (size_t)b * N_ * INNER + h * 64;
        for (int i = t; i < N_; i += 256) {
            const float4* r4 = (const float4*)(base + (size_t)i * INNER);
            float s = 0.f;
#pragma unroll
            for (int q = 0; q < 16; q++) {
                float4 v = r4[q];
                s += v.x * v.x + v.y * v.y + v.z * v.z + v.w * v.w;
            }
            nrm[i] = sqrtf(s);
        }
        __syncthreads();
        float mx = 0.f;
        for (int i = t; i < N_; i += 256) mx = fmaxf(mx, nrm[i]);
        for (int o = 16; o; o >>= 1) mx = fmaxf(mx, __shfl_xor_sync(~0u, mx, o));
        if ((t & 31) == 0) red[t >> 5] = mx;
        __syncthreads();
        if (t == 0) {
            float m = red[0];
#pragma unroll
            for (int w = 1; w < 8; w++) m = fmaxf(m, red[w]);
            smax = m;
        }
        __syncthreads();
        const float c = SCALE * LOG2E * smax;
        for (int i = t; i < N_; i += 256)
            g_ml[g * N_ + i] = c * nrm[i];
    }
}

// ---------------------------------------------------------------------------
// K2 (lstats): lidar row sums with fixed bound. fp16+LDSM, 1 sync/iter.
// ---------------------------------------------------------------------------
__global__ __launch_bounds__(256) void k_lstats(const float* __restrict__ lidar) {
    extern __shared__ __half smh[];
    __half* Ali = smh;                    // 128*72
    __half* BsA = smh + 9216;             // 2 x 128*72
    float* mls = (float*)(smh + 27648);
    float* red = mls + 128;               // 512
    const int t = threadIdx.x, warp = t >> 5, lane = t & 31;
    const int g8 = lane >> 2, t4 = lane & 3;
    const int gidx = blockIdx.y, b = gidx >> 3, h = gidx & 7;
    const int i0 = blockIdx.x * 128;
    const float* base = lidar + (size_t)b * N_ * INNER + h * 64;
    const int wm = warp >> 2, wn = warp & 3;
    R4T ra, rb;
    ldg4(ra, base + (size_t)i0 * INNER, INNER);
    sts4h<72, 0>(Ali, ra, SCALE * LOG2E);
    ldg4(ra, base + (size_t)i0 * INNER + 32, INNER);
    sts4h<72, 32>(Ali, ra, SCALE * LOG2E);
    if (t < 128) mls[t] = g_ml[gidx * N_ + i0 + t];
    ldg4(ra, base, INNER);
    ldg4(rb, base + 32, INNER);
    sts4h<72, 0>(BsA, ra, 1.f);
    sts4h<72, 32>(BsA, rb, 1.f);
    ldg4(ra, base + (size_t)128 * INNER, INNER);
    ldg4(rb, base + (size_t)128 * INNER + 32, INNER);
    __syncthreads();
    int cur = 0;
    float lp[4][2] = {};
    for (int jt = 0; jt < 8; jt++) {
        __half* bnext = BsA + (cur ^ 1) * 9216;
        sts4h<72, 0>(bnext, ra, 1.f);
        sts4h<72, 32>(bnext, rb, 1.f);
        {
            const float* nxt = base + (size_t)(((jt + 2) & 7) * 128) * INNER;
            ldg4(ra, nxt, INNER);
            ldg4(rb, nxt + 32, INNER);
        }
        float acc[4][4][4] = {};
        mma_h<4, 4, 4, 4, 72, 72>(Ali, BsA + cur * 9216, warp, lane, acc);
#pragma unroll
        for (int mt = 0; mt < 4; mt++) {
            int r = wm * 64 + mt * 16 + g8;
            float mn0 = mls[r], mn1 = mls[r + 8];
            float s0 = 0.f, s1 = 0.f;
#pragma unroll
            for (int nt = 0; nt < 4; nt++) {
                s0 += ex2f(acc[mt][nt][0] - mn0) + ex2f(acc[mt][nt][1] - mn0);
                s1 += ex2f(acc[mt][nt][2] - mn1) + ex2f(acc[mt][nt][3] - mn1);
            }
            lp[mt][0] += s0; lp[mt][1] += s1;
        }
        __syncthreads();
        cur ^= 1;
    }
#pragma unroll
    for (int mt = 0; mt < 4; mt++) {
        float s0 = lp[mt][0], s1 = lp[mt][1];
#pragma unroll
        for (int off = 1; off <= 2; off <<= 1) {
            s0 += __shfl_xor_sync(~0u, s0, off);
            s1 += __shfl_xor_sync(~0u, s1, off);
        }
        if (t4 == 0) {
            red[wn * 128 + wm * 64 + mt * 16 + g8] = s0;
            red[wn * 128 + wm * 64 + mt * 16 + g8 + 8] = s1;
        }
    }
    __syncthreads();
    if (t < 128)
        g_isl[gidx * N_ + i0 + t] =
            1.0f / (red[t] + red[128 + t] + red[256 + t] + red[384 + t]);
}

// ---------------------------------------------------------------------------
// K3 (flash, split-KV, fp16, P-in-registers): warps 4x2 (32 rows x 64 cols).
// P C-fragments recast as PV A-fragments; no Ps smem. 3 barriers/iter.
// ---------------------------------------------------------------------------
__global__ __launch_bounds__(256, 1) void k_flash(const float* __restrict__ lidar,
                                                  const float* __restrict__ conv_w) {
    extern __shared__ __half smh[];
    __half* AliL = smh;                   // 128*72
    __half* AliQ = smh + 9216;            // 128*72
    __half* Bs0  = smh + 18432;           // 128*72
    __half* Bs1  = smh + 27648;           // 128*72
    __half* Vs   = smh + 36864;           // 64*136 (d-major, j contiguous)
    float* mls  = (float*)(smh + 45568);
    float* isls = mls + 128;
    float* m_s  = isls + 128;
    float* red  = m_s + 128;              // 256
    float* Os   = (float*)smh;            // epilogue alias: 128 x 68

    const int t = threadIdx.x, warp = t >> 5, lane = t & 31;
    const int g8 = lane >> 2, t4 = lane & 3;
    const int gidx = blockIdx.y, i0 = blockIdx.x * 128;
    const int jh = blockIdx.z;
    const int b = gidx >> 3, h = gidx & 7;
    const float c0s = conv_w[0] * SCALE * LOG2E;
    const float c1L = conv_w[1] * LOG2E;
    const int wm = warp >> 1, wn = warp & 1;   // 4x2 layout

    if (t < 128) {
        mls[t] = g_ml[gidx * N_ + i0 + t];
        isls[t] = g_isl[gidx * N_ + i0 + t];
        m_s[t] = g_mi[gidx * N_ + i0 + t];
    }
    const float* lbase = lidar + (size_t)b * N_ * INNER + h * 64;
    const float* qb = g_q + (size_t)gidx * N_ * DH;
    const float* kb = g_k + (size_t)gidx * N_ * DH;
    const float* vb = g_vT + (size_t)gidx * DH * N_;

    R4T ra, rb;
    ldg4(ra, lbase + (size_t)i0 * INNER, INNER);      sts4h<72, 0>(AliL, ra, SCALE * LOG2E);
    ldg4(ra, lbase + (size_t)i0 * INNER + 32, INNER); sts4h<72, 32>(AliL, ra, SCALE * LOG2E);
    ldg4(ra, qb + (size_t)i0 * DH, DH);               sts4h<72, 0>(AliQ, ra, c0s);
    ldg4(ra, qb + (size_t)i0 * DH + 32, DH);          sts4h<72, 32>(AliQ, ra, c0s);
    const int jstart = jh * 512;
    ldg4(ra, lbase + (size_t)jstart * INNER, INNER);
    ldg4(rb, lbase + (size_t)jstart * INNER + 32, INNER);
    sts4h<72, 0>(Bs0, ra, 1.f);
    sts4h<72, 32>(Bs0, rb, 1.f);
    ldg4(ra, kb + (size_t)jstart * DH, DH);
    ldg4(rb, kb + (size_t)jstart * DH + 32, DH);
    __syncthreads();

    float acc_o[2][8][4] = {};   // partial O: 32 rows x 64 d (this warp's j-slice)
    float lp[2][2] = {};
    float4 vreg[8];

    const int vd = t >> 2;                 // 0..63
    const int vj = (t & 3) * 4;            // j base within 16-group

    // PV B fragment base: Vs rows = d, cols = j (k dim); warp's k-slice = wn*64
    const int brow = lane & 7;
    const int bcol = ((lane >> 3) & 1) * 8;
    const uint32_t vbase = (uint32_t)__cvta_generic_to_shared(
        Vs + brow * 136 + wn * 64 + bcol);

    for (int j0 = jstart; j0 < jstart + 512; j0 += 128) {
        float acc[2][8][4] = {};
        // --- step 1: lidar mma (Bs0); stage k (Bs1); ldg V
        mma_h<2, 8, 2, 4, 72, 72>(AliL, Bs0, warp, lane, acc);
#pragma unroll
        for (int mt = 0; mt < 2; mt++) {
            int r = wm * 32 + mt * 16 + g8;
            float m0v = mls[r], i0v = isls[r] * c1L;
            float m1v = mls[r + 8], i1v = isls[r + 8] * c1L;
#pragma unroll
            for (int nt = 0; nt < 8; nt++) {
                acc[mt][nt][0] = i0v * ex2f(acc[mt][nt][0] - m0v);
                acc[mt][nt][1] = i0v * ex2f(acc[mt][nt][1] - m0v);
                acc[mt][nt][2] = i1v * ex2f(acc[mt][nt][2] - m1v);
                acc[mt][nt][3] = i1v * ex2f(acc[mt][nt][3] - m1v);
            }
        }
        sts4h<72, 0>(Bs1, ra, 1.f);
        sts4h<72, 32>(Bs1, rb, 1.f);
        {
            const float* src = vb + (size_t)vd * N_ + j0 + vj;
#pragma unroll
            for (int q = 0; q < 8; q++)
                vreg[q] = *(const float4*)(src + q * 16);
        }
        __syncthreads();                               // (1) Bs1 ready
        // --- step 2: qk mma (Bs1); P -> half2 A-frags in regs; stage V
        mma_h<2, 8, 2, 4, 72, 72>(AliQ, Bs1, warp, lane, acc);
        unsigned pf[2][4][4];   // [mt][ks][frag]
#pragma unroll
        for (int mt = 0; mt < 2; mt++) {
            int r = wm * 32 + mt * 16 + g8;
            float mn0 = m_s[r], mn1 = m_s[r + 8];
            float s0 = 0.f, s1 = 0.f;
#pragma unroll
            for (int ks = 0; ks < 4; ks++) {
                float p00 = ex2f(acc[mt][2 * ks][0] - mn0);
                float p01 = ex2f(acc[mt][2 * ks][1] - mn0);
                float p02 = ex2f(acc[mt][2 * ks][2] - mn1);
                float p03 = ex2f(acc[mt][2 * ks][3] - mn1);
                float p10 = ex2f(acc[mt][2 * ks + 1][0] - mn0);
                float p11 = ex2f(acc[mt][2 * ks + 1][1] - mn0);
                float p12 = ex2f(acc[mt][2 * ks + 1][2] - mn1);
                float p13 = ex2f(acc[mt][2 * ks + 1][3] - mn1);
                s0 += p00 + p01 + p10 + p11;
                s1 += p02 + p03 + p12 + p13;
                __half2 h0 = __floats2half2_rn(p00, p01);
                __half2 h1 = __floats2half2_rn(p02, p03);
                __half2 h2v = __floats2half2_rn(p10, p11);
                __half2 h3 = __floats2half2_rn(p12, p13);
                pf[mt][ks][0] = *(unsigned*)&h0;
                pf[mt][ks][1] = *(unsigned*)&h1;
                pf[mt][ks][2] = *(unsigned*)&h2v;
                pf[mt][ks][3] = *(unsigned*)&h3;
            }
            lp[mt][0] += s0; lp[mt][1] += s1;
        }
#pragma unroll
        for (int q = 0; q < 8; q++) {
            float4 v = vreg[q];
            __half* rp = Vs + vd * 136 + vj + q * 16;
            *(__half2*)rp = __floats2half2_rn(v.x, v.y);
            *(__half2*)(rp + 2) = __floats2half2_rn(v.z, v.w);
        }
        {
            const float* nxt = lbase + (size_t)((j0 + 128) & (N_ - 1)) * INNER;
            ldg4(ra, nxt, INNER);
            ldg4(rb, nxt + 32, INNER);
        }
        __syncthreads();                               // (2) Vs ready
        // --- step 3: PV mma from register P; stage next lidar (Bs0); ldg next k
#pragma unroll
        for (int ks = 0; ks < 4; ks++) {
            unsigned bf[8][2];
#pragma unroll
            for (int nt = 0; nt < 8; nt++)
                ldsm2(bf[nt], vbase + (nt * 8 * 136 + ks * 16) * 2);
#pragma unroll
            for (int mt = 0; mt < 2; mt++)
#pragma unroll
                for (int nt = 0; nt < 8; nt++)
                    mma16(acc_o[mt][nt], pf[mt][ks], bf[nt]);
        }
        sts4h<72, 0>(Bs0, ra, 1.f);
        sts4h<72, 32>(Bs0, rb, 1.f);
        {
            const float* nxt = kb + (size_t)((j0 + 128) & (N_ - 1)) * DH;
            ldg4(ra, nxt, DH);
            ldg4(rb, nxt + 32, DH);
        }
        __syncthreads();                               // (3) Bs0 ready
    }
    // row-sum reduction (partials over this warp's 64-col slice, sum over wn)
#pragma unroll
    for (int mt = 0; mt < 2; mt++) {
        float s0 = lp[mt][0], s1 = lp[mt][1];
#pragma unroll
        for (int off = 1; off <= 2; off <<= 1) {
            s0 += __shfl_xor_sync(~0u, s0, off);
            s1 += __shfl_xor_sync(~0u, s1, off);
        }
        if (t4 == 0) {
            red[wn * 128 + wm * 32 + mt * 16 + g8] = s0;
            red[wn * 128 + wm * 32 + mt * 16 + g8 + 8] = s1;
        }
    }
    __syncthreads();
    if (t < 128)
        g_lacc[jh * G * N_ + gidx * N_ + i0 + t] = red[t] + red[128 + t];
    __syncthreads();   // before Os aliases tile smem
    // combine wn halves of O via smem
    if (wn == 1) {
#pragma unroll
        for (int mt = 0; mt < 2; mt++) {
            int r = wm * 32 + mt * 16 + g8;
#pragma unroll
            for (int nt = 0; nt < 8; nt++) {
                int d = nt * 8 + 2 * t4;
                *(float2*)&Os[r * 68 + d] =
                    make_float2(acc_o[mt][nt][0], acc_o[mt][nt][1]);
                *(float2*)&Os[(r + 8) * 68 + d] =
                    make_float2(acc_o[mt][nt][2], acc_o[mt][nt][3]);
            }
        }
    }
    __syncthreads();
    if (wn == 0) {
        float* ob = g_oacc + (size_t)jh * G * N_ * DH +
                    ((size_t)gidx * N_ + i0) * DH;
#pragma unroll
        for (int mt = 0; mt < 2; mt++) {
            int r = wm * 32 + mt * 16 + g8;
#pragma unroll
            for (int nt = 0; nt < 8; nt++) {
                int d = nt * 8 + 2 * t4;
                float2 o0 = *(float2*)&Os[r * 68 + d];
                float2 o1 = *(float2*)&Os[(r + 8) * 68 + d];
                *(float2*)&ob[(size_t)r * DH + d] =
                    make_float2(acc_o[mt][nt][0] + o0.x, acc_o[mt][nt][1] + o0.y);
                *(float2*)&ob[(size_t)(r + 8) * DH + d] =
                    make_float2(acc_o[mt][nt][2] + o1.x, acc_o[mt][nt][3] + o1.y);
            }
        }
    }
}

// ---------------------------------------------------------------------------
// K3b: combine split-KV partials -> g_y (scattered layout)
// ---------------------------------------------------------------------------
__global__ __launch_bounds__(256) void k_combine() {
    int idx = blockIdx.x * 256 + threadIdx.x;
    int g = idx >> 14;
    int rem = idx & 16383;
    int n = rem >> 4;
    int d4 = (rem & 15) * 4;
    float l = g_lacc[g * N_ + n] + g_lacc[G * N_ + g * N_ + n];
    float inv = 1.0f / l;
    size_t off = ((size_t)g * N_ + n) * DH + d4;
    float4 o0 = *(const float4*)&g_oacc[off];
    float4 o1 = *(const float4*)&g_oacc[(size_t)G * N_ * DH + off];
    int b = g >> 3, h = g & 7;
    float* dst = g_y + ((size_t)b * N_ + n) * INNER + h * 64 + d4;
    *(float4*)dst = make_float4((o0.x + o1.x) * inv, (o0.y + o1.y) * inv,
                                (o0.z + o1.z) * inv, (o0.w + o1.w) * inv);
}

// ---------------------------------------------------------------------------
// K4: out = y @ W2^T + bias2  (fp16 HMMA, double-buffered)
// ---------------------------------------------------------------------------
__global__ __launch_bounds__(256) void k_out(float* __restrict__ out) {
    __shared__ __half As[2][128 * 40], Bs[2][128 * 40];
    const int t = threadIdx.x, warp = t >> 5, lane = t & 31;
    const int g8 = lane >> 2, t4 = lane & 3;
    const int n0 = blockIdx.x * 128, m0 = blockIdx.y * 128;
    float acc[4][4][4] = {};
    R4T ra, rb;
    ldg4(ra, g_y + (size_t)m0 * INNER, INNER);
    ldg4(rb, g_w2 + (size_t)n0 * INNER, INNER);
    sts4h<40, 0>(As[0], ra, 1.f);
    sts4h<40, 0>(Bs[0], rb, 1.f);
    __syncthreads();
    int cur = 0;
    for (int k0 = 32; k0 < INNER; k0 += 32) {
        ldg4(ra, g_y + (size_t)m0 * INNER + k0, INNER);
        ldg4(rb, g_w2 + (size_t)n0 * INNER + k0, INNER);
        mma_h<4, 4, 4, 2, 40, 40>(As[cur], Bs[cur], warp, lane, acc);
        sts4h<40, 0>(As[cur ^ 1], ra, 1.f);
        sts4h<40, 0>(Bs[cur ^ 1], rb, 1.f);
        __syncthreads();
        cur ^= 1;
    }
    mma_h<4, 4, 4, 2, 40, 40>(As[cur], Bs[cur], warp, lane, acc);
    const int wm = warp >> 2, wn = warp & 3;
#pragma unroll
    for (int mt = 0; mt < 4; mt++)
#pragma unroll
        for (int nt = 0; nt < 4; nt++) {
            int col = n0 + wn * 32 + nt * 8 + 2 * t4;
            float b0 = g_b2[col], b1 = g_b2[col + 1];
            int r = m0 + wm * 64 + mt * 16 + g8;
            *(float2*)&out[(size_t)r * DIM + col] =
                make_float2(acc[mt][nt][0] + b0, acc[mt][nt][1] + b1);
            *(float2*)&out[(size_t)(r + 8) * DIM + col] =
                make_float2(acc[mt][nt][2] + b0, acc[mt][nt][3] + b1);
        }
}

// ---------------------------------------------------------------------------
// Precompute: W2 = Wout(.,h-block) @ Wm ; bias2 = b_out + Wout b_merge~
// ---------------------------------------------------------------------------
__global__ __launch_bounds__(256) void k_w2(const float* __restrict__ w_merge,
                                            const float* __restrict__ w_out) {
    __shared__ float wm[64 * 64];
    const int t = threadIdx.x;
    for (int i = t; i < 4096; i += 256) wm[i] = w_merge[i];
    __syncthreads();
    int idx = blockIdx.x * 256 + t;
    int c = idx >> 9, i = idx & 511;
    int h = i >> 6, d = i & 63;
    const float* wo = w_out + (size_t)c * INNER + h * 64;
    float s = 0.f;
#pragma unroll 8
    for (int dp = 0; dp < 64; dp++) s += wo[dp] * wm[dp * 64 + d];
    g_w2[idx] = s;
}

__global__ __launch_bounds__(256) void k_bias2(const float* __restrict__ w_out,
                                               const float* __restrict__ b_merge,
                                               const float* __restrict__ b_out) {
    int c = blockIdx.x * 8 + (threadIdx.x >> 5);
    int lane = threadIdx.x & 31;
    float s = 0.f;
    for (int i = lane; i < INNER; i += 32)
        s += w_out[(size_t)c * INNER + i] * b_merge[i & 63];
    for (int o = 16; o; o >>= 1) s += __shfl_xor_sync(~0u, s, o);
    if (lane == 0) g_b2[c] = b_out[c] + s;
}

__global__ __launch_bounds__(256) void k_copy(const float* __restrict__ src,
                                              float* __restrict__ dst, int n4) {
    int i = blockIdx.x * blockDim.x + threadIdx.x;
    if (i < n4) ((float4*)dst)[i] = ((const float4*)src)[i];
}

extern "C" void kernel_launch(void* const* d_in, const int* in_sizes, int n_in,
                              void* d_out, int out_size) {
    const float* x       = (const float*)d_in[0];
    const float* lidar   = (const float*)d_in[1];
    const float* w_qkv   = (const float*)d_in[2];
    const float* w_merge = (const float*)d_in[3];
    const float* b_merge = (const float*)d_in[4];
    const float* w_out   = (const float*)d_in[5];
    const float* b_out   = (const float*)d_in[6];
    const float* conv_w  = (const float*)d_in[7];
    float* out = (float*)d_out;

    const int flashSmem = 45568 * 2 + (3 * 128 + 256) * 4;   // ~91.6 KB
    const int lstatsSmem = 27648 * 2 + (128 + 512) * 4;      // ~57.9 KB
    cudaFuncSetAttribute(k_flash, cudaFuncAttributeMaxDynamicSharedMemorySize,
                         flashSmem);
    cudaFuncSetAttribute(k_lstats, cudaFuncAttributeMaxDynamicSharedMemorySize,
                         lstatsSmem);

    // launch order keeps k_flash 4th (ncu captures launch #4)
    k_qkv<<<dim3(12, 64), 256>>>(x, w_qkv);
    k_bounds<<<dim3(G, 2), 256>>>(conv_w, lidar);
    k_lstats<<<dim3(8, G), 256, lstatsSmem>>>(lidar);
    k_flash<<<dim3(8, G, 2), 256, flashSmem>>>(lidar, conv_w);
    k_w2<<<1024, 256>>>(w_merge, w_out);
    k_bias2<<<64, 256>>>(w_out, b_merge, b_out);
    k_combine<<<4096, 256>>>();
    k_out<<<dim3(4, 64), 256>>>(out);

    const int outElems = B_ * N_ * DIM;
    if (out_size >= 2 * outElems)
        k_copy<<<(outElems / 4 + 255) / 256, 256>>>(lidar, out + outElems,
                                                    outElems / 4);
}